// round 1
// baseline (speedup 1.0000x reference)
#include <cuda_runtime.h>
#include <cuda_bf16.h>
#include <cstdint>

// Problem constants (fixed by the dataset)
#define NN   50000
#define EE   800000
#define C    128
#define COUT 64
#define EPSV 1e-5f

// ---------------- device scratch (no allocations allowed) ----------------
__device__ float g_deg[NN];          // degree, then dis = rsqrt(deg)
__device__ int   g_cnt[NN];          // incoming-edge counts
__device__ int   g_rowstart[NN + 1]; // CSR row offsets (by dst)
__device__ int   g_cursor[NN];       // fill cursors
__device__ int   g_col[EE];          // CSR col = src node
__device__ float g_wv[EE];           // CSR edge norm weight
__device__ float g_tmp[(size_t)NN * C];
__device__ float g_bufA[(size_t)NN * C];
__device__ float g_bufB[(size_t)NN * C];
__device__ float g_bnA[3 * C];       // per-channel scale (BN folded)
__device__ float g_bnB[3 * C];       // per-channel shift (bias+BN folded)

__device__ __forceinline__ float* bufsel(int b) {
    return (b == 0) ? g_tmp : ((b == 1) ? g_bufA : g_bufB);
}

// ---------------- setup kernels ----------------
__global__ void init_kernel(int n) {
    int i = blockIdx.x * blockDim.x + threadIdx.x;
    if (i < n) { g_deg[i] = 1.0f; g_cnt[i] = 0; }   // deg starts at 1 (self loop)
}

__global__ void count_kernel(const int* __restrict__ dst, const float* __restrict__ ew, int e) {
    int i = blockIdx.x * blockDim.x + threadIdx.x;
    if (i < e) {
        int d = dst[i];
        atomicAdd(&g_cnt[d], 1);
        atomicAdd(&g_deg[d], ew[i]);
    }
}

// single-block exclusive scan of g_cnt -> g_rowstart (n up to 50000)
__global__ void scan_kernel(int n) {
    __shared__ int wsum[32];
    __shared__ int carry;
    int t = threadIdx.x, lane = t & 31, w = t >> 5;
    if (t == 0) carry = 0;
    __syncthreads();
    for (int base = 0; base < n; base += 1024) {
        int i = base + t;
        int v = (i < n) ? g_cnt[i] : 0;
        int x = v;
        #pragma unroll
        for (int o = 1; o < 32; o <<= 1) { int y = __shfl_up_sync(0xffffffffu, x, o); if (lane >= o) x += y; }
        if (lane == 31) wsum[w] = x;
        __syncthreads();
        if (w == 0) {
            int s = wsum[lane];
            #pragma unroll
            for (int o = 1; o < 32; o <<= 1) { int y = __shfl_up_sync(0xffffffffu, s, o); if (lane >= o) s += y; }
            wsum[lane] = s;
        }
        __syncthreads();
        int incl = x + (w > 0 ? wsum[w - 1] : 0) + carry;
        if (i < n) g_rowstart[i] = incl - v;
        __syncthreads();                 // all done reading wsum/carry
        if (t == 1023) carry = incl;     // chunk total (incl. old carry)
        __syncthreads();
    }
    if (t == 0) g_rowstart[n] = carry;
}

__global__ void dis_kernel(int n) {
    int i = blockIdx.x * blockDim.x + threadIdx.x;
    if (i < n) {
        float d = g_deg[i];
        g_deg[i] = (d > 0.0f) ? rsqrtf(d) : 0.0f;   // now holds dis
        g_cursor[i] = g_rowstart[i];
    }
}

__global__ void fill_kernel(const int* __restrict__ src, const int* __restrict__ dst,
                            const float* __restrict__ ew, int e) {
    int i = blockIdx.x * blockDim.x + threadIdx.x;
    if (i < e) {
        int s = src[i], d = dst[i];
        int pos = atomicAdd(&g_cursor[d], 1);
        g_col[pos] = s;
        g_wv[pos]  = g_deg[s] * ew[i] * g_deg[d];
    }
}

// fold BN (+ conv bias) into per-channel scale/shift:  h = sum*A + B
__global__ void bnparam_kernel(const float* b1,
                               const float* g1, const float* be1, const float* m1, const float* v1,
                               const float* conv_bs,
                               const float* gs, const float* bes, const float* ms, const float* vs) {
    int c = threadIdx.x;
    if (c < C) {
        float sc = g1[c] * rsqrtf(v1[c] + EPSV);
        g_bnA[c] = sc;
        g_bnB[c] = be1[c] + (b1[c] - m1[c]) * sc;
        #pragma unroll
        for (int l = 0; l < 2; l++) {
            float s2 = gs[l * C + c] * rsqrtf(vs[l * C + c] + EPSV);
            g_bnA[(1 + l) * C + c] = s2;
            g_bnB[(1 + l) * C + c] = bes[l * C + c] + (conv_bs[l * C + c] - ms[l * C + c]) * s2;
        }
    }
}

// ---------------- SGEMM: Out[M,Ncols] = A[M,128] @ W[128,Ncols] ----------------
// EPI: 0 = raw, 1 = +bias,leakyrelu, 2 = +bias
#define BM 128
#define BN 128
#define BK 32
#define SPITCH (BM + 4)

template <int EPI>
__global__ __launch_bounds__(256) void gemm_kernel(int abuf, const float* __restrict__ Aext,
                                                   const float* __restrict__ W,
                                                   const float* __restrict__ bias,
                                                   float* __restrict__ Outext, int obuf,
                                                   int M, int Ncols) {
    const float* A = (abuf >= 0) ? bufsel(abuf) : Aext;
    float* Out = Outext ? Outext : bufsel(obuf);

    __shared__ float As[BK][SPITCH];   // transposed: As[k][m]
    __shared__ float Bs[BK][SPITCH];   // Bs[k][n]

    int t = threadIdx.x;
    int tx = t & 15, ty = t >> 4;      // 16 x 16 thread grid, 8x8 microtile
    int m0 = blockIdx.x * BM;

    float acc[8][8];
    #pragma unroll
    for (int i = 0; i < 8; i++)
        #pragma unroll
        for (int j = 0; j < 8; j++) acc[i][j] = 0.0f;

    int c4a = t & 7, ra = t >> 3;      // A tile loader: 128 rows x 8 float4
    int c4b = t & 31, rb = t >> 5;     // B tile loader: 32 rows x 32 float4

    #pragma unroll 1
    for (int kt = 0; kt < 128; kt += BK) {
        // load A tile (with transpose)
        #pragma unroll
        for (int j = 0; j < 4; j++) {
            int row = ra + 32 * j;
            int m = m0 + row;
            float4 av = make_float4(0.f, 0.f, 0.f, 0.f);
            if (m < M) av = *reinterpret_cast<const float4*>(&A[(size_t)m * 128 + kt + c4a * 4]);
            As[c4a * 4 + 0][row] = av.x;
            As[c4a * 4 + 1][row] = av.y;
            As[c4a * 4 + 2][row] = av.z;
            As[c4a * 4 + 3][row] = av.w;
        }
        // load B tile
        #pragma unroll
        for (int j = 0; j < 4; j++) {
            int krow = rb + 8 * j;
            int col = c4b * 4;
            float4 bv = make_float4(0.f, 0.f, 0.f, 0.f);
            if (col < Ncols)
                bv = *reinterpret_cast<const float4*>(&W[(size_t)(kt + krow) * Ncols + col]);
            *reinterpret_cast<float4*>(&Bs[krow][col]) = bv;
        }
        __syncthreads();

        #pragma unroll 16
        for (int kk = 0; kk < BK; kk++) {
            float4 a0 = *reinterpret_cast<const float4*>(&As[kk][ty * 8]);
            float4 a1 = *reinterpret_cast<const float4*>(&As[kk][ty * 8 + 4]);
            float4 b0 = *reinterpret_cast<const float4*>(&Bs[kk][tx * 8]);
            float4 b1 = *reinterpret_cast<const float4*>(&Bs[kk][tx * 8 + 4]);
            float a[8] = {a0.x, a0.y, a0.z, a0.w, a1.x, a1.y, a1.z, a1.w};
            float b[8] = {b0.x, b0.y, b0.z, b0.w, b1.x, b1.y, b1.z, b1.w};
            #pragma unroll
            for (int i = 0; i < 8; i++)
                #pragma unroll
                for (int j = 0; j < 8; j++) acc[i][j] += a[i] * b[j];
        }
        __syncthreads();
    }

    // epilogue
    #pragma unroll
    for (int i = 0; i < 8; i++) {
        int m = m0 + ty * 8 + i;
        if (m < M) {
            #pragma unroll
            for (int jj = 0; jj < 8; jj += 4) {
                int ncol = tx * 8 + jj;
                if (ncol < Ncols) {
                    float4 v = make_float4(acc[i][jj], acc[i][jj + 1], acc[i][jj + 2], acc[i][jj + 3]);
                    if (EPI >= 1) {
                        v.x += bias[ncol]; v.y += bias[ncol + 1];
                        v.z += bias[ncol + 2]; v.w += bias[ncol + 3];
                    }
                    if (EPI == 1) {
                        v.x = v.x > 0.f ? v.x : 0.01f * v.x;
                        v.y = v.y > 0.f ? v.y : 0.01f * v.y;
                        v.z = v.z > 0.f ? v.z : 0.01f * v.z;
                        v.w = v.w > 0.f ? v.w : 0.01f * v.w;
                    }
                    *reinterpret_cast<float4*>(&Out[(size_t)m * Ncols + ncol]) = v;
                }
            }
        }
    }
}

// ---------------- CSR gather + BN + residual + leakyReLU ----------------
// out[i][c] = lrelu( (selfnorm*tmp[i][c] + sum_e w_e*tmp[col_e][c]) * A[c] + B[c] + resid[i][c] )
__global__ __launch_bounds__(128) void gather_kernel(int tmpbuf, int residbuf, int outbuf,
                                                     int layer, int n) {
    const float* __restrict__ tmp = bufsel(tmpbuf);
    float* __restrict__ out = bufsel(outbuf);
    int i = blockIdx.x;
    if (i >= n) return;
    int c = threadIdx.x;

    float dis_i = g_deg[i];
    float acc = dis_i * dis_i * tmp[(size_t)i * C + c];

    int s = g_rowstart[i], e = g_rowstart[i + 1];
    int k = s;
    for (; k + 4 <= e; k += 4) {
        int s0 = __ldg(&g_col[k]),     s1 = __ldg(&g_col[k + 1]);
        int s2 = __ldg(&g_col[k + 2]), s3 = __ldg(&g_col[k + 3]);
        float w0 = __ldg(&g_wv[k]),     w1 = __ldg(&g_wv[k + 1]);
        float w2 = __ldg(&g_wv[k + 2]), w3 = __ldg(&g_wv[k + 3]);
        float v0 = tmp[(size_t)s0 * C + c];
        float v1 = tmp[(size_t)s1 * C + c];
        float v2 = tmp[(size_t)s2 * C + c];
        float v3 = tmp[(size_t)s3 * C + c];
        acc += w0 * v0 + w1 * v1 + w2 * v2 + w3 * v3;
    }
    for (; k < e; k++)
        acc += __ldg(&g_wv[k]) * tmp[(size_t)__ldg(&g_col[k]) * C + c];

    float y = acc * g_bnA[layer * C + c] + g_bnB[layer * C + c];
    if (residbuf >= 0) y += bufsel(residbuf)[(size_t)i * C + c];
    out[(size_t)i * C + c] = (y > 0.f) ? y : 0.01f * y;
}

// ---------------- launch ----------------
extern "C" void kernel_launch(void* const* d_in, const int* in_sizes, int n_in,
                              void* d_out, int out_size) {
    const float* x       = (const float*)d_in[0];
    const int*   ei      = (const int*)d_in[1];
    const float* ew      = (const float*)d_in[2];
    const float* w1      = (const float*)d_in[3];
    const float* b1      = (const float*)d_in[4];
    const float* bn1_g   = (const float*)d_in[5];
    const float* bn1_b   = (const float*)d_in[6];
    const float* bn1_m   = (const float*)d_in[7];
    const float* bn1_v   = (const float*)d_in[8];
    const float* conv_ws = (const float*)d_in[9];
    const float* conv_bs = (const float*)d_in[10];
    const float* bns_g   = (const float*)d_in[11];
    const float* bns_b   = (const float*)d_in[12];
    const float* bns_m   = (const float*)d_in[13];
    const float* bns_v   = (const float*)d_in[14];
    const float* lin1_w  = (const float*)d_in[15];
    const float* lin1_b  = (const float*)d_in[16];
    const float* lin2_w  = (const float*)d_in[17];
    const float* lin2_b  = (const float*)d_in[18];

    int n = in_sizes[0] / C;     // 50000
    int e = in_sizes[2];         // 800000
    const int* srcp = ei;
    const int* dstp = ei + e;

    // graph preprocessing: degrees, CSR by dst, normalized edge weights
    init_kernel<<<(n + 255) / 256, 256>>>(n);
    count_kernel<<<(e + 255) / 256, 256>>>(dstp, ew, e);
    scan_kernel<<<1, 1024>>>(n);
    dis_kernel<<<(n + 255) / 256, 256>>>(n);
    fill_kernel<<<(e + 255) / 256, 256>>>(srcp, dstp, ew, e);
    bnparam_kernel<<<1, 128>>>(b1, bn1_g, bn1_b, bn1_m, bn1_v,
                               conv_bs, bns_g, bns_b, bns_m, bns_v);

    int gblocks = (n + BM - 1) / BM;

    // layer 0: tmp = x @ w1 ; bufA = lrelu(bn0(aggregate(tmp)))
    gemm_kernel<0><<<gblocks, 256>>>(-1, x, w1, nullptr, nullptr, 0, n, 128);
    gather_kernel<<<n, 128>>>(0, -1, 1, 0, n);

    // layer 1: tmp = bufA @ conv_ws[0] ; bufB = lrelu(bn1(agg(tmp)) + bufA)
    gemm_kernel<0><<<gblocks, 256>>>(1, nullptr, conv_ws, nullptr, nullptr, 0, n, 128);
    gather_kernel<<<n, 128>>>(0, 1, 2, 1, n);

    // layer 2: tmp = bufB @ conv_ws[1] ; bufA = lrelu(bn2(agg(tmp)) + bufB)
    gemm_kernel<0><<<gblocks, 256>>>(2, nullptr, conv_ws + 128 * 128, nullptr, nullptr, 0, n, 128);
    gather_kernel<<<n, 128>>>(0, 2, 1, 2, n);

    // heads: bufB = lrelu(bufA @ lin1_w + lin1_b) ; out = bufB @ lin2_w + lin2_b
    gemm_kernel<1><<<gblocks, 256>>>(1, nullptr, lin1_w, lin1_b, nullptr, 2, n, 128);
    gemm_kernel<2><<<gblocks, 256>>>(2, nullptr, lin2_w, lin2_b, (float*)d_out, -1, n, 64);
}

// round 3
// speedup vs baseline: 1.5963x; 1.5963x over previous
#include <cuda_runtime.h>
#include <cuda_bf16.h>
#include <cstdint>

// Problem constants (fixed by the dataset)
#define NN   50000
#define EE   800000
#define C    128
#define COUT 64
#define EPSV 1e-5f

// ---------------- device scratch (no allocations allowed) ----------------
__device__ float g_deg[NN];          // degree, then dis = rsqrt(deg)
__device__ int   g_cnt[NN];          // incoming-edge counts
__device__ int   g_rowstart[NN + 1]; // CSR row offsets (by dst)
__device__ int   g_cursor[NN];       // fill cursors
__device__ int   g_col[EE];          // CSR col = src node
__device__ float g_wv[EE];           // CSR edge norm weight
__device__ float g_tmp[(size_t)NN * C];
__device__ float g_bufA[(size_t)NN * C];
__device__ float g_bufB[(size_t)NN * C];
__device__ float g_bnA[3 * C];       // per-channel scale (BN folded)
__device__ float g_bnB[3 * C];       // per-channel shift (bias+BN folded)
__device__ float g_wt[5 * 128 * 128]; // transposed weights WT[n][k], tf32-rounded

__device__ __forceinline__ float* bufsel(int b) {
    return (b == 0) ? g_tmp : ((b == 1) ? g_bufA : g_bufB);
}

__device__ __forceinline__ float to_tf32(float f) {
    uint32_t u;
    asm("cvt.rna.tf32.f32 %0, %1;" : "=r"(u) : "f"(f));
    return __uint_as_float(u);
}

__device__ __forceinline__ void mma8(float* d, const uint32_t* a, const uint32_t* b) {
    asm volatile(
        "mma.sync.aligned.m16n8k8.row.col.f32.tf32.tf32.f32 "
        "{%0,%1,%2,%3}, {%4,%5,%6,%7}, {%8,%9}, {%0,%1,%2,%3};"
        : "+f"(d[0]), "+f"(d[1]), "+f"(d[2]), "+f"(d[3])
        : "r"(a[0]), "r"(a[1]), "r"(a[2]), "r"(a[3]), "r"(b[0]), "r"(b[1]));
}

// ---------------- setup kernels ----------------
// init degrees/counts AND transpose the 5 weight matrices into g_wt (tf32-rounded)
__global__ void init_tr_kernel(int n, const float* __restrict__ w1,
                               const float* __restrict__ conv_ws,
                               const float* __restrict__ lin1_w,
                               const float* __restrict__ lin2_w) {
    int nb_init = (n + 255) / 256;
    if ((int)blockIdx.x < nb_init) {
        int i = blockIdx.x * 256 + threadIdx.x;
        if (i < n) { g_deg[i] = 1.0f; g_cnt[i] = 0; }   // deg starts at 1 (self loop)
        return;
    }
    int g = (blockIdx.x - nb_init) * 256 + threadIdx.x;
    if (g < 4 * 16384) {
        int mat = g >> 14, idx = g & 16383;
        int k = idx >> 7, nn = idx & 127;
        const float* W = (mat == 0) ? w1 : ((mat == 3) ? lin1_w : (conv_ws + (mat - 1) * 16384));
        g_wt[mat * 16384 + nn * 128 + k] = to_tf32(W[k * 128 + nn]);
    } else if (g < 4 * 16384 + 8192) {
        int idx = g - 4 * 16384;
        int k = idx >> 6, nn = idx & 63;
        g_wt[4 * 16384 + nn * 128 + k] = to_tf32(lin2_w[k * 64 + nn]);
    }
}

__global__ void count_kernel(const int* __restrict__ dst, const float* __restrict__ ew, int e) {
    int i = blockIdx.x * blockDim.x + threadIdx.x;
    if (i < e) {
        int d = dst[i];
        atomicAdd(&g_cnt[d], 1);
        atomicAdd(&g_deg[d], ew[i]);
    }
}

// single-block exclusive scan of g_cnt -> g_rowstart
__global__ void scan_kernel(int n) {
    __shared__ int wsum[32];
    __shared__ int carry;
    int t = threadIdx.x, lane = t & 31, w = t >> 5;
    if (t == 0) carry = 0;
    __syncthreads();
    for (int base = 0; base < n; base += 1024) {
        int i = base + t;
        int v = (i < n) ? g_cnt[i] : 0;
        int x = v;
        #pragma unroll
        for (int o = 1; o < 32; o <<= 1) { int y = __shfl_up_sync(0xffffffffu, x, o); if (lane >= o) x += y; }
        if (lane == 31) wsum[w] = x;
        __syncthreads();
        if (w == 0) {
            int s = wsum[lane];
            #pragma unroll
            for (int o = 1; o < 32; o <<= 1) { int y = __shfl_up_sync(0xffffffffu, s, o); if (lane >= o) s += y; }
            wsum[lane] = s;
        }
        __syncthreads();
        int incl = x + (w > 0 ? wsum[w - 1] : 0) + carry;
        if (i < n) g_rowstart[i] = incl - v;
        __syncthreads();
        if (t == 1023) carry = incl;
        __syncthreads();
    }
    if (t == 0) g_rowstart[n] = carry;
}

// dis = rsqrt(deg), cursors, AND fold BN params (block 0, first 128 threads)
__global__ void disbn_kernel(int n, const float* b1,
                             const float* g1, const float* be1, const float* m1, const float* v1,
                             const float* conv_bs,
                             const float* gs, const float* bes, const float* ms, const float* vs) {
    int i = blockIdx.x * blockDim.x + threadIdx.x;
    if (i < n) {
        float d = g_deg[i];
        g_deg[i] = (d > 0.0f) ? rsqrtf(d) : 0.0f;
        g_cursor[i] = g_rowstart[i];
    }
    if (blockIdx.x == 0 && threadIdx.x < C) {
        int c = threadIdx.x;
        float sc = g1[c] * rsqrtf(v1[c] + EPSV);
        g_bnA[c] = sc;
        g_bnB[c] = be1[c] + (b1[c] - m1[c]) * sc;
        #pragma unroll
        for (int l = 0; l < 2; l++) {
            float s2 = gs[l * C + c] * rsqrtf(vs[l * C + c] + EPSV);
            g_bnA[(1 + l) * C + c] = s2;
            g_bnB[(1 + l) * C + c] = bes[l * C + c] + (conv_bs[l * C + c] - ms[l * C + c]) * s2;
        }
    }
}

__global__ void fill_kernel(const int* __restrict__ src, const int* __restrict__ dst,
                            const float* __restrict__ ew, int e) {
    int i = blockIdx.x * blockDim.x + threadIdx.x;
    if (i < e) {
        int s = src[i], d = dst[i];
        int pos = atomicAdd(&g_cursor[d], 1);
        g_col[pos] = s;
        g_wv[pos]  = g_deg[s] * ew[i] * g_deg[d];
    }
}

// ---------------- mma.sync tf32 GEMM: Out[M,NC] = A[M,128] @ W[128,NC] ----------------
// 256 threads = 8 warps as 4(M) x 2(N); warp tile 32 x NC/2; m16n8k8 fragments.
// A staged in SMEM (tf32-rounded); W read from pre-transposed tf32 g_wt.
// EPI: 0 = raw, 1 = +bias,leakyrelu, 2 = +bias
#define APITCH 132

template <int NC, int EPI>
__global__ __launch_bounds__(256) void mma_gemm_kernel(int abuf, const float* __restrict__ Aext,
                                                       const float* __restrict__ WT,
                                                       const float* __restrict__ bias,
                                                       float* __restrict__ Outext, int obuf, int M) {
    extern __shared__ float sm[];
    float* As = sm;                    // [128][APITCH]
    float* Ws = sm + 128 * APITCH;     // [NC][APITCH]

    const float* A = (abuf >= 0) ? bufsel(abuf) : Aext;
    float* Out = Outext ? Outext : bufsel(obuf);

    int tid = threadIdx.x;
    int m0 = blockIdx.x * 128;

    // stage A (tf32-rounded) : 128 rows x 32 float4
    #pragma unroll
    for (int it = 0; it < 16; it++) {
        int idx = tid + it * 256;
        int r = idx >> 5, q = idx & 31;
        int m = m0 + r;
        float4 v = make_float4(0.f, 0.f, 0.f, 0.f);
        if (m < M) v = *reinterpret_cast<const float4*>(&A[(size_t)m * 128 + q * 4]);
        float* p = &As[r * APITCH + q * 4];
        p[0] = to_tf32(v.x); p[1] = to_tf32(v.y); p[2] = to_tf32(v.z); p[3] = to_tf32(v.w);
    }
    // stage W (already tf32) : NC rows x 32 float4
    #pragma unroll
    for (int it = 0; it < NC / 8; it++) {
        int idx = tid + it * 256;
        int r = idx >> 5, q = idx & 31;
        float4 v = *reinterpret_cast<const float4*>(&WT[(size_t)r * 128 + q * 4]);
        *reinterpret_cast<float4*>(&Ws[r * APITCH + q * 4]) = v;
    }
    __syncthreads();

    int wid = tid >> 5, lane = tid & 31;
    int wm = wid & 3, wn = wid >> 2;          // 4 x 2 warp grid
    constexpr int NF = NC / 16;               // n-fragments per warp (8 or 4)
    constexpr int WN = NC / 2;

    float d[2][NF][4];
    #pragma unroll
    for (int i = 0; i < 2; i++)
        #pragma unroll
        for (int j = 0; j < NF; j++)
            #pragma unroll
            for (int q = 0; q < 4; q++) d[i][j][q] = 0.0f;

    int grp = lane >> 2, tg = lane & 3;
    int arow = wm * 32 + grp;                 // A fragment base row
    int brow = wn * WN + grp;                 // B fragment base n

    #pragma unroll
    for (int k0 = 0; k0 < 16; k0++) {
        int kk = k0 * 8 + tg;
        uint32_t a[2][4];
        #pragma unroll
        for (int mf = 0; mf < 2; mf++) {
            const float* ap = &As[(arow + mf * 16) * APITCH + kk];
            a[mf][0] = __float_as_uint(ap[0]);
            a[mf][2] = __float_as_uint(ap[4]);
            a[mf][1] = __float_as_uint(ap[8 * APITCH]);
            a[mf][3] = __float_as_uint(ap[8 * APITCH + 4]);
        }
        uint32_t b[NF][2];
        #pragma unroll
        for (int nf = 0; nf < NF; nf++) {
            const float* bp = &Ws[(brow + nf * 8) * APITCH + kk];
            b[nf][0] = __float_as_uint(bp[0]);
            b[nf][1] = __float_as_uint(bp[4]);
        }
        #pragma unroll
        for (int mf = 0; mf < 2; mf++)
            #pragma unroll
            for (int nf = 0; nf < NF; nf++)
                mma8(d[mf][nf], a[mf], b[nf]);
    }

    // epilogue: D fragment (row=grp[+8], col=tg*2[+1])
    #pragma unroll
    for (int mf = 0; mf < 2; mf++) {
        #pragma unroll
        for (int half = 0; half < 2; half++) {
            int m = m0 + wm * 32 + mf * 16 + half * 8 + grp;
            if (m < M) {
                #pragma unroll
                for (int nf = 0; nf < NF; nf++) {
                    int ncol = wn * WN + nf * 8 + tg * 2;
                    float2 v;
                    v.x = d[mf][nf][half * 2 + 0];
                    v.y = d[mf][nf][half * 2 + 1];
                    if (EPI >= 1) { v.x += bias[ncol]; v.y += bias[ncol + 1]; }
                    if (EPI == 1) {
                        v.x = v.x > 0.f ? v.x : 0.01f * v.x;
                        v.y = v.y > 0.f ? v.y : 0.01f * v.y;
                    }
                    *reinterpret_cast<float2*>(&Out[(size_t)m * NC + ncol]) = v;
                }
            }
        }
    }
}

// ---------------- CSR gather + BN + residual + leakyReLU ----------------
__global__ __launch_bounds__(128) void gather_kernel(int tmpbuf, int residbuf, int outbuf,
                                                     int layer, int n) {
    const float* __restrict__ tmp = bufsel(tmpbuf);
    float* __restrict__ out = bufsel(outbuf);
    int i = blockIdx.x;
    if (i >= n) return;
    int c = threadIdx.x;

    float dis_i = g_deg[i];
    float acc = dis_i * dis_i * tmp[(size_t)i * C + c];

    int s = g_rowstart[i], e = g_rowstart[i + 1];
    int k = s;
    for (; k + 4 <= e; k += 4) {
        int s0 = __ldg(&g_col[k]),     s1 = __ldg(&g_col[k + 1]);
        int s2 = __ldg(&g_col[k + 2]), s3 = __ldg(&g_col[k + 3]);
        float w0 = __ldg(&g_wv[k]),     w1 = __ldg(&g_wv[k + 1]);
        float w2 = __ldg(&g_wv[k + 2]), w3 = __ldg(&g_wv[k + 3]);
        float v0 = tmp[(size_t)s0 * C + c];
        float v1 = tmp[(size_t)s1 * C + c];
        float v2 = tmp[(size_t)s2 * C + c];
        float v3 = tmp[(size_t)s3 * C + c];
        acc += w0 * v0 + w1 * v1 + w2 * v2 + w3 * v3;
    }
    for (; k < e; k++)
        acc += __ldg(&g_wv[k]) * tmp[(size_t)__ldg(&g_col[k]) * C + c];

    float y = acc * g_bnA[layer * C + c] + g_bnB[layer * C + c];
    if (residbuf >= 0) y += bufsel(residbuf)[(size_t)i * C + c];
    out[(size_t)i * C + c] = (y > 0.f) ? y : 0.01f * y;
}

// ---------------- launch ----------------
extern "C" void kernel_launch(void* const* d_in, const int* in_sizes, int n_in,
                              void* d_out, int out_size) {
    const float* x       = (const float*)d_in[0];
    const int*   ei      = (const int*)d_in[1];
    const float* ew      = (const float*)d_in[2];
    const float* w1      = (const float*)d_in[3];
    const float* b1      = (const float*)d_in[4];
    const float* bn1_g   = (const float*)d_in[5];
    const float* bn1_b   = (const float*)d_in[6];
    const float* bn1_m   = (const float*)d_in[7];
    const float* bn1_v   = (const float*)d_in[8];
    const float* conv_ws = (const float*)d_in[9];
    const float* conv_bs = (const float*)d_in[10];
    const float* bns_g   = (const float*)d_in[11];
    const float* bns_b   = (const float*)d_in[12];
    const float* bns_m   = (const float*)d_in[13];
    const float* bns_v   = (const float*)d_in[14];
    const float* lin1_w  = (const float*)d_in[15];
    const float* lin1_b  = (const float*)d_in[16];
    const float* lin2_w  = (const float*)d_in[17];
    const float* lin2_b  = (const float*)d_in[18];

    int n = in_sizes[0] / C;     // 50000
    int e = in_sizes[2];         // 800000
    const int* srcp = ei;
    const int* dstp = ei + e;

    const int SMEM128 = (128 + 128) * APITCH * 4;
    const int SMEM64  = (128 + 64) * APITCH * 4;

    static bool attr_done = false;
    if (!attr_done) {
        cudaFuncSetAttribute(mma_gemm_kernel<128, 0>, cudaFuncAttributeMaxDynamicSharedMemorySize, SMEM128);
        cudaFuncSetAttribute(mma_gemm_kernel<128, 1>, cudaFuncAttributeMaxDynamicSharedMemorySize, SMEM128);
        cudaFuncSetAttribute(mma_gemm_kernel<64, 2>,  cudaFuncAttributeMaxDynamicSharedMemorySize, SMEM64);
        attr_done = true;
    }

    // preprocessing (5 launches before first GEMM -> ncu -s 5 captures GEMM)
    int nb_init = (n + 255) / 256;
    init_tr_kernel<<<nb_init + (5 * 16384 - 8192 + 255) / 256, 256>>>(n, w1, conv_ws, lin1_w, lin2_w);
    count_kernel<<<(e + 255) / 256, 256>>>(dstp, ew, e);
    scan_kernel<<<1, 1024>>>(n);
    disbn_kernel<<<nb_init, 256>>>(n, b1, bn1_g, bn1_b, bn1_m, bn1_v,
                                   conv_bs, bns_g, bns_b, bns_m, bns_v);
    fill_kernel<<<(e + 255) / 256, 256>>>(srcp, dstp, ew, e);

    int gblocks = (n + 127) / 128;
    float* wt = nullptr;
    cudaGetSymbolAddress((void**)&wt, g_wt);

    // layer 0: tmp = x @ w1 ; bufA = lrelu(bn0(aggregate(tmp)))
    mma_gemm_kernel<128, 0><<<gblocks, 256, SMEM128>>>(-1, x, wt + 0 * 16384, nullptr, nullptr, 0, n);
    gather_kernel<<<n, 128>>>(0, -1, 1, 0, n);

    // layer 1: tmp = bufA @ conv_ws[0] ; bufB = lrelu(bn1(agg(tmp)) + bufA)
    mma_gemm_kernel<128, 0><<<gblocks, 256, SMEM128>>>(1, nullptr, wt + 1 * 16384, nullptr, nullptr, 0, n);
    gather_kernel<<<n, 128>>>(0, 1, 2, 1, n);

    // layer 2: tmp = bufB @ conv_ws[1] ; bufA = lrelu(bn2(agg(tmp)) + bufB)
    mma_gemm_kernel<128, 0><<<gblocks, 256, SMEM128>>>(2, nullptr, wt + 2 * 16384, nullptr, nullptr, 0, n);
    gather_kernel<<<n, 128>>>(0, 2, 1, 2, n);

    // heads: bufB = lrelu(bufA @ lin1_w + lin1_b) ; out = bufB @ lin2_w + lin2_b
    mma_gemm_kernel<128, 1><<<gblocks, 256, SMEM128>>>(1, nullptr, wt + 3 * 16384, lin1_b, nullptr, 2, n);
    mma_gemm_kernel<64, 2><<<gblocks, 256, SMEM64>>>(2, nullptr, wt + 4 * 16384, lin2_b, (float*)d_out, -1, n);
}